// round 3
// baseline (speedup 1.0000x reference)
#include <cuda_runtime.h>
#include <math.h>

#define NEG 0.01f
typedef unsigned long long ull;

// ---------------- packed f32x2 helpers ----------------
__device__ __forceinline__ ull pk2(float lo, float hi) {
    ull r; asm("mov.b64 %0,{%1,%2};" : "=l"(r) : "f"(lo), "f"(hi)); return r;
}
__device__ __forceinline__ void upk2(ull v, float& lo, float& hi) {
    asm("mov.b64 {%0,%1},%2;" : "=f"(lo), "=f"(hi) : "l"(v));
}
__device__ __forceinline__ ull ffma2(ull a, ull b, ull c) {
    ull d; asm("fma.rn.f32x2 %0,%1,%2,%3;" : "=l"(d) : "l"(a), "l"(b), "l"(c)); return d;
}

// ---------------- scratch (device globals; no runtime allocation) ----------------
__device__ float g_bufA[64L*256*2048];   // main activations
__device__ float g_bufB[64L*256*1024];   // conv1 output / flut-pvc conv scratch
__device__ float g_bufP[64L*256*1024];   // pooled identity input
__device__ float g_bufC[64L*256*1024];   // identity conv output
__device__ float g_qkv [64L*768*64];
__device__ float g_att [64L*256*64];
__device__ float g_hm  [64L*256*64];
__device__ float g_xmain[64*256];
__device__ float g_fvec[64*4096];
__device__ float g_pvec[64*2048];
__device__ float g_f2[64*64];
__device__ float g_p2[64*32];
__device__ float g_freq[64*32];
__device__ float2 g_tw[4096];
__device__ float g_bn[8192];
__device__ float g_wT[6535680];          // transposed weights

// g_wT offsets (floats)
#define O_CONV0   0L
#define O_RC1     46080L
#define O_RC2     2995200L
#define O_RID     5944320L
#define O_MHAIN   6272000L
#define O_MHAOUT  6468608L
#define O_FLUT    6534144L
#define O_PVC     6535104L

// ---------------- BN folding ----------------
__global__ void prep_kernel(const float* __restrict__ bn0,
                            const float* __restrict__ rbn1,
                            const float* __restrict__ rbn2,
                            const float* __restrict__ fbn, const float* __restrict__ fb,
                            const float* __restrict__ pbn, const float* __restrict__ pb)
{
    int c = threadIdx.x;
    if (c < 256) {
        {
            float g = bn0[c], b = bn0[256+c], m = bn0[512+c], v = bn0[768+c];
            float s = g * rsqrtf(v + 1e-5f);
            g_bn[c] = s; g_bn[256+c] = b - m*s;
        }
        for (int i = 0; i < 5; i++) {
            const float* p1 = rbn1 + i*1024;
            float g = p1[c], b = p1[256+c], m = p1[512+c], v = p1[768+c];
            float s = g * rsqrtf(v + 1e-5f);
            g_bn[512 + i*256 + c] = s; g_bn[1792 + i*256 + c] = b - m*s;
            const float* p2 = rbn2 + i*1024;
            g = p2[c]; b = p2[256+c]; m = p2[512+c]; v = p2[768+c];
            s = g * rsqrtf(v + 1e-5f);
            g_bn[3072 + i*256 + c] = s; g_bn[4352 + i*256 + c] = b - m*s;
        }
    }
    if (c < 64) {
        float g = fbn[c], b = fbn[64+c], m = fbn[128+c], v = fbn[192+c];
        float s = g * rsqrtf(v + 1e-5f);
        g_bn[5632+c] = s; g_bn[5696+c] = (fb[c] - m)*s + b;
        g = pbn[c]; b = pbn[64+c]; m = pbn[128+c]; v = pbn[192+c];
        s = g * rsqrtf(v + 1e-5f);
        g_bn[5760+c] = s; g_bn[5824+c] = (pb[c] - m)*s + b;
    }
}

// ---------------- weight transpose into SMEM-stage layout ----------------
__global__ void wtrans_kernel(const float* __restrict__ src, float* __restrict__ dst,
                              int CI, int KW, long total)
{
    long i = (long)blockIdx.x*256 + threadIdx.x;
    if (i >= total) return;
    int co64 = (int)(i & 63);
    long r = i >> 6;
    int k = (int)(r % KW); r /= KW;
    int ci = (int)(r % CI);
    long ct = r / CI;
    long co = ct*64 + co64;
    dst[i] = src[(co*CI + ci)*KW + k];
}

// ---------------- implicit-GEMM conv1d, f32x2 math, double-buffered staging ----------------
// tile: 64 co x TT t, 256 threads. COT co x 4 t per thread.
template<int KW, int STRIDE, int CB, int TT>
__global__ void __launch_bounds__(256, 2) conv_gemm(
    const float* __restrict__ wT, const float* __restrict__ in,
    const float* __restrict__ scale, const float* __restrict__ bias,
    const float* __restrict__ addb, float* __restrict__ out, float* __restrict__ poolout,
    int CI, int CO, int Lin, int Lout, int pad, int dorelu, long inBS)
{
    constexpr int WIN  = TT*STRIDE + KW - 1;
    constexpr int WINP = (WIN + 23) & ~7;
    constexpr int NTX  = TT/4;              // threads along t
    constexpr int COT  = 64 / (256/NTX);    // co per thread (TT=128 -> 8, TT=64 -> 4)
    constexpr int RW   = 3*STRIDE + KW;
    constexpr int NV   = (RW + 3) / 4;
    __shared__ __align__(16) float sW[2][CB*KW*64];
    __shared__ __align__(16) float sIn[2][CB][WINP];

    const int tid = threadIdx.x;
    const int tx = tid % NTX, ty = tid / NTX;
    const int t0 = blockIdx.x * TT, co0 = blockIdx.y * 64;
    const int b  = blockIdx.z;
    const float* inb = in + (long)b * inBS;
    const long wstride = (long)KW * 64;
    const float* wbase = wT + (long)blockIdx.y * CI * wstride;

    ull acc[COT/2][4];
    #pragma unroll
    for (int i = 0; i < COT/2; i++)
        #pragma unroll
        for (int j = 0; j < 4; j++) acc[i][j] = 0ull;

    const int nst = CI / CB;
    auto stage = [&](int buf, int cib) {
        const float4* ws = (const float4*)(wbase + (long)cib * wstride);
        float4* wd = (float4*)sW[buf];
        for (int idx = tid; idx < CB*KW*16; idx += 256) wd[idx] = ws[idx];
        for (int idx = tid; idx < CB*WIN; idx += 256) {
            int c = idx / WIN, w = idx - c*WIN;
            int g = t0*STRIDE - pad + w;
            sIn[buf][c][w] = (g >= 0 && g < Lin) ? __ldg(&inb[(long)(cib+c)*Lin + g]) : 0.f;
        }
    };

    stage(0, 0);
    __syncthreads();
    for (int s = 0; s < nst; s++) {
        int cur = s & 1;
        if (s + 1 < nst) stage(cur ^ 1, (s + 1) * CB);
        #pragma unroll
        for (int c = 0; c < CB; c++) {
            float4 wv4[NV];
            const float4* ip = (const float4*)&sIn[cur][c][tx*4*STRIDE];
            #pragma unroll
            for (int v = 0; v < NV; v++) wv4[v] = ip[v];
            const float* wf = (const float*)wv4;
            ull bc[RW];
            #pragma unroll
            for (int m = 0; m < RW; m++) bc[m] = pk2(wf[m], wf[m]);
            const float* wrow = sW[cur] + c*KW*64 + ty*COT;
            #pragma unroll
            for (int k = 0; k < KW; k++) {
                ull wv[COT/2];
                #pragma unroll
                for (int v = 0; v < COT/4; v++) {
                    ulonglong2 t2 = *(const ulonglong2*)(wrow + k*64 + v*4);
                    wv[2*v] = t2.x; wv[2*v+1] = t2.y;
                }
                #pragma unroll
                for (int j = 0; j < 4; j++)
                    #pragma unroll
                    for (int i = 0; i < COT/2; i++)
                        acc[i][j] = ffma2(wv[i], bc[j*STRIDE + k], acc[i][j]);
            }
        }
        __syncthreads();
    }

    // epilogue
    #pragma unroll
    for (int i2 = 0; i2 < COT/2; i2++) {
        float r0[4], r1[4];
        #pragma unroll
        for (int j = 0; j < 4; j++) upk2(acc[i2][j], r0[j], r1[j]);
        #pragma unroll
        for (int half = 0; half < 2; half++) {
            const float* rr = half ? r1 : r0;
            int co = co0 + ty*COT + i2*2 + half;
            float sc = scale ? scale[co] : 1.f;
            float bb = bias  ? bias[co]  : 0.f;
            long obase = ((long)b*CO + co) * Lout + t0 + tx*4;
            float4 v;
            v.x = rr[0]*sc + bb; v.y = rr[1]*sc + bb;
            v.z = rr[2]*sc + bb; v.w = rr[3]*sc + bb;
            if (dorelu) {
                v.x = v.x >= 0.f ? v.x : NEG*v.x; v.y = v.y >= 0.f ? v.y : NEG*v.y;
                v.z = v.z >= 0.f ? v.z : NEG*v.z; v.w = v.w >= 0.f ? v.w : NEG*v.w;
            }
            if (addb) {
                float4 a = *(const float4*)&addb[obase];
                v.x += a.x; v.y += a.y; v.z += a.z; v.w += a.w;
            }
            *(float4*)&out[obase] = v;
            if (poolout) {
                long pbase = ((long)b*CO + co) * (Lout >> 1) + (t0 >> 1) + tx*2;
                *(float2*)&poolout[pbase] = make_float2(0.5f*(v.x + v.y), 0.5f*(v.z + v.w));
            }
        }
    }
}

// ---------------- attention per (batch, head): S=64, d=32 ----------------
__global__ void __launch_bounds__(128) attn_kernel(const float* __restrict__ qkv,
                                                   float* __restrict__ out)
{
    __shared__ float q[32][64], kk[32][64], vv[32][64];
    __shared__ float att[64][65];
    int bh = blockIdx.x; int b = bh >> 3, h = bh & 7;
    const float* base = qkv + (long)b*768*64 + (long)h*32*64;
    int tid = threadIdx.x;
    for (int idx = tid; idx < 2048; idx += 128) {
        int d = idx >> 6, s = idx & 63;
        q [d][s] = base[d*64 + s];
        kk[d][s] = base[256*64 + d*64 + s];
        vv[d][s] = base[512*64 + d*64 + s];
    }
    __syncthreads();
    for (int e = tid; e < 4096; e += 128) {
        int qs = e >> 6, ks = e & 63;
        float s = 0.f;
        #pragma unroll
        for (int d = 0; d < 32; d++) s = fmaf(q[d][qs], kk[d][ks], s);
        att[qs][ks] = s * 0.17677669529663687f;
    }
    __syncthreads();
    if (tid < 64) {
        float m = -1e30f;
        for (int ks = 0; ks < 64; ks++) m = fmaxf(m, att[tid][ks]);
        float sum = 0.f;
        for (int ks = 0; ks < 64; ks++) { float e = expf(att[tid][ks] - m); att[tid][ks] = e; sum += e; }
        float inv = 1.f / sum;
        for (int ks = 0; ks < 64; ks++) att[tid][ks] *= inv;
    }
    __syncthreads();
    float* ob = out + (long)b*256*64 + (long)h*32*64;
    for (int e = tid; e < 2048; e += 128) {
        int d = e >> 6, qs = e & 63;
        float s = 0.f;
        #pragma unroll
        for (int ks = 0; ks < 64; ks++) s = fmaf(att[qs][ks], vv[d][ks], s);
        ob[d*64 + qs] = s;
    }
}

// ---------------- max over t (T=64) ----------------
__global__ void max_t_kernel(const float* __restrict__ in, float* __restrict__ out)
{
    int b = blockIdx.x, c = threadIdx.x;
    const float* r = in + ((long)b*256 + c) * 64;
    float m = r[0];
    #pragma unroll
    for (int t = 1; t < 64; t++) m = fmaxf(m, r[t]);
    out[b*256 + c] = m;
}

// ---------------- grouped max along L ----------------
__global__ void group_max_kernel(const float* __restrict__ in, float* __restrict__ out, int GS)
{
    int row = blockIdx.x; int g = threadIdx.x; int G = blockDim.x;
    const float* r = in + (long)row*G*GS + (long)g*GS;
    float m = r[0];
    for (int j = 1; j < GS; j++) m = fmaxf(m, r[j]);
    out[(long)row*G + g] = m;
}

// ---------------- small dense (per-batch) ----------------
__global__ void dense_kernel(const float* __restrict__ in, const float* __restrict__ w,
                             const float* __restrict__ bias, float* __restrict__ out,
                             int IN, int OUT, int dorelu)
{
    int b = blockIdx.x, o = threadIdx.x;
    if (o >= OUT) return;
    const float* iv = in + (long)b*IN;
    const float* wr = w + (long)o*IN;
    float s = bias ? bias[o] : 0.f;
    for (int i = 0; i < IN; i++) s = fmaf(iv[i], wr[i], s);
    if (dorelu) s = (s >= 0.f) ? s : NEG*s;
    out[b*OUT + o] = s;
}

// ---------------- twiddle table ----------------
__global__ void twiddle_kernel()
{
    int i = blockIdx.x*256 + threadIdx.x;
    if (i < 4096) {
        double a = -2.0 * 3.14159265358979323846 * (double)i / 4096.0;
        g_tw[i] = make_float2((float)cos(a), (float)sin(a));
    }
}

// ---------------- DFT bins 50..305 + normalize + freq dense ----------------
__global__ void __launch_bounds__(256) fft_freq_kernel(const float* __restrict__ x,
                                                       const float* __restrict__ fw,
                                                       const float* __restrict__ fb,
                                                       float* __restrict__ out)
{
    __shared__ float2 stw[4096];
    __shared__ float smag[256];
    __shared__ float sred[256];
    int b = blockIdx.x, tid = threadIdx.x;
    for (int i = tid; i < 4096; i += 256) stw[i] = g_tw[i];
    const float* xr = x + ((long)b*12 + 1) * 4096;
    __syncthreads();
    int k = 50 + tid;
    float re = 0.f, im = 0.f;
    for (int n = 0; n < 4096; n++) {
        float xv = __ldg(&xr[n]);
        float2 c = stw[(k*n) & 4095];
        re = fmaf(xv, c.x, re);
        im = fmaf(xv, c.y, im);
    }
    float mag = sqrtf(re*re + im*im);
    smag[tid] = mag; sred[tid] = mag;
    __syncthreads();
    for (int s = 128; s > 0; s >>= 1) {
        if (tid < s) sred[tid] = fmaxf(sred[tid], sred[tid+s]);
        __syncthreads();
    }
    float mx = sred[0];
    smag[tid] = (mx > 0.f) ? mag/mx : mag;
    __syncthreads();
    if (tid < 32) {
        float s = fb[tid];
        const float* wr = fw + tid*256;
        for (int j = 0; j < 256; j++) s = fmaf(smag[j], wr[j], s);
        out[b*32 + tid] = (s >= 0.f) ? s : NEG*s;
    }
}

// ---------------- concat + FC + sigmoid ----------------
__global__ void final_kernel(const float* __restrict__ xm, const float* __restrict__ l,
                             const float* __restrict__ fq, const float* __restrict__ f2,
                             const float* __restrict__ p2, const float* __restrict__ fcw,
                             const float* __restrict__ fcb, float* __restrict__ out)
{
    __shared__ float comb[396];
    int b = blockIdx.x, tid = threadIdx.x;
    for (int i = tid; i < 256; i += 128) comb[i] = xm[b*256 + i];
    if (tid < 12) comb[256 + tid] = l[b*12 + tid];
    if (tid < 32) comb[268 + tid] = fq[b*32 + tid];
    if (tid < 64) comb[300 + tid] = f2[b*64 + tid];
    if (tid < 32) comb[364 + tid] = p2[b*32 + tid];
    __syncthreads();
    if (tid < 27) {
        float s = fcb[tid];
        const float* wr = fcw + tid*396;
        for (int j = 0; j < 396; j++) s = fmaf(comb[j], wr[j], s);
        out[b*27 + tid] = s;
        out[64*27 + b*27 + tid] = 1.f / (1.f + expf(-s));
    }
}

// ---------------- host launch ----------------
extern "C" void kernel_launch(void* const* d_in, const int* in_sizes, int n_in,
                              void* d_out, int out_size)
{
    (void)in_sizes; (void)n_in; (void)out_size;
    const float* x      = (const float*)d_in[0];
    const float* l      = (const float*)d_in[1];
    const float* conv_w = (const float*)d_in[2];
    const float* bn0    = (const float*)d_in[3];
    const float* rc1    = (const float*)d_in[4];
    const float* rbn1   = (const float*)d_in[5];
    const float* rc2    = (const float*)d_in[6];
    const float* rbn2   = (const float*)d_in[7];
    const float* rid    = (const float*)d_in[8];
    const float* miw    = (const float*)d_in[9];
    const float* mib    = (const float*)d_in[10];
    const float* mow    = (const float*)d_in[11];
    const float* mob    = (const float*)d_in[12];
    const float* fw     = (const float*)d_in[13];
    const float* fbv    = (const float*)d_in[14];
    const float* fbn    = (const float*)d_in[15];
    const float* pw     = (const float*)d_in[16];
    const float* pbv    = (const float*)d_in[17];
    const float* pbn    = (const float*)d_in[18];
    const float* wflut2 = (const float*)d_in[19];
    const float* wpvc2  = (const float*)d_in[20];
    const float* freqw  = (const float*)d_in[21];
    const float* freqb  = (const float*)d_in[22];
    const float* fcw    = (const float*)d_in[23];
    const float* fcb    = (const float*)d_in[24];

    float *A, *Bf, *P, *C, *QKV, *ATT, *HM, *XM, *FV, *PV, *F2, *P2, *FQ, *BN, *WT;
    cudaGetSymbolAddress((void**)&A,   g_bufA);
    cudaGetSymbolAddress((void**)&Bf,  g_bufB);
    cudaGetSymbolAddress((void**)&P,   g_bufP);
    cudaGetSymbolAddress((void**)&C,   g_bufC);
    cudaGetSymbolAddress((void**)&QKV, g_qkv);
    cudaGetSymbolAddress((void**)&ATT, g_att);
    cudaGetSymbolAddress((void**)&HM,  g_hm);
    cudaGetSymbolAddress((void**)&XM,  g_xmain);
    cudaGetSymbolAddress((void**)&FV,  g_fvec);
    cudaGetSymbolAddress((void**)&PV,  g_pvec);
    cudaGetSymbolAddress((void**)&F2,  g_f2);
    cudaGetSymbolAddress((void**)&P2,  g_p2);
    cudaGetSymbolAddress((void**)&FQ,  g_freq);
    cudaGetSymbolAddress((void**)&BN,  g_bn);
    cudaGetSymbolAddress((void**)&WT,  g_wT);

    prep_kernel<<<1, 256>>>(bn0, rbn1, rbn2, fbn, fbv, pbn, pbv);
    twiddle_kernel<<<16, 256>>>();

    auto wt = [&](const float* src, long off, int CO, int CI, int KW) {
        long tot = (long)CO*CI*KW;
        wtrans_kernel<<<(unsigned)((tot + 255)/256), 256>>>(src, WT + off, CI, KW, tot);
    };
    wt(conv_w, O_CONV0, 256, 12, 15);
    wt(rc1,    O_RC1,   1280, 256, 9);
    wt(rc2,    O_RC2,   1280, 256, 9);
    wt(rid,    O_RID,   1280, 256, 1);
    wt(miw,    O_MHAIN,  768, 256, 1);
    wt(mow,    O_MHAOUT, 256, 256, 1);
    wt(fw,     O_FLUT,    64,   1, 15);
    wt(pw,     O_PVC,     64,   1, 9);

    // conv0: (B,12,4096) -> (B,256,2048), fused avgpool2 -> P
    conv_gemm<15,2,4,64><<<dim3(32,4,64), 256>>>(WT+O_CONV0, x, BN+0, BN+256, nullptr, A, P,
                                                 12, 256, 4096, 2048, 7, 1, 12L*4096);

    int L = 2048;
    for (int i = 0; i < 5; i++) {
        int Lh = L/2;
        if (Lh >= 128) {
            conv_gemm<9,2,4,128><<<dim3(Lh/128,4,64), 256>>>(WT+O_RC1 + (long)i*589824, A,
                BN+512+i*256, BN+1792+i*256, nullptr, Bf, nullptr, 256, 256, L, Lh, 4, 1, 256L*L);
            conv_gemm<1,1,8,128><<<dim3(Lh/128,4,64), 256>>>(WT+O_RID + (long)i*65536, P,
                nullptr, nullptr, nullptr, C, nullptr, 256, 256, Lh, Lh, 0, 0, 256L*Lh);
            conv_gemm<9,1,4,128><<<dim3(Lh/128,4,64), 256>>>(WT+O_RC2 + (long)i*589824, Bf,
                BN+3072+i*256, BN+4352+i*256, C, A, P, 256, 256, Lh, Lh, 4, 1, 256L*Lh);
        } else {
            conv_gemm<9,2,4,64><<<dim3(Lh/64,4,64), 256>>>(WT+O_RC1 + (long)i*589824, A,
                BN+512+i*256, BN+1792+i*256, nullptr, Bf, nullptr, 256, 256, L, Lh, 4, 1, 256L*L);
            conv_gemm<1,1,8,64><<<dim3(Lh/64,4,64), 256>>>(WT+O_RID + (long)i*65536, P,
                nullptr, nullptr, nullptr, C, nullptr, 256, 256, Lh, Lh, 0, 0, 256L*Lh);
            conv_gemm<9,1,4,64><<<dim3(Lh/64,4,64), 256>>>(WT+O_RC2 + (long)i*589824, Bf,
                BN+3072+i*256, BN+4352+i*256, C, A, P, 256, 256, Lh, Lh, 4, 1, 256L*Lh);
        }
        L = Lh;
    }

    // MHA
    conv_gemm<1,1,8,64><<<dim3(1,12,64), 256>>>(WT+O_MHAIN, A, nullptr, mib, nullptr, QKV, nullptr,
                                                256, 768, 64, 64, 0, 0, 256L*64);
    attn_kernel<<<512, 128>>>(QKV, ATT);
    conv_gemm<1,1,8,64><<<dim3(1,4,64), 256>>>(WT+O_MHAOUT, ATT, nullptr, mob, nullptr, HM, nullptr,
                                               256, 256, 64, 64, 0, 0, 256L*64);
    max_t_kernel<<<64, 256>>>(HM, XM);

    // FLUT path (lead II)
    conv_gemm<15,2,1,64><<<dim3(32,1,64), 256>>>(WT+O_FLUT, x + 4096, BN+5632, BN+5696, nullptr, Bf, nullptr,
                                                 1, 64, 4096, 2048, 7, 1, 12L*4096);
    group_max_kernel<<<64*64, 64>>>(Bf, FV, 32);
    dense_kernel<<<64, 64>>>(FV, wflut2, nullptr, F2, 4096, 64, 1);

    // PVC path
    conv_gemm<9,2,1,64><<<dim3(32,1,64), 256>>>(WT+O_PVC, x + 4096, BN+5760, BN+5824, nullptr, Bf, nullptr,
                                                1, 64, 4096, 2048, 4, 1, 12L*4096);
    group_max_kernel<<<64*64, 32>>>(Bf, PV, 64);
    dense_kernel<<<64, 64>>>(PV, wpvc2, nullptr, P2, 2048, 32, 1);

    // FFT + freq dense
    fft_freq_kernel<<<64, 256>>>(x, freqw, freqb, FQ);

    // concat + FC + sigmoid
    final_kernel<<<64, 128>>>(XM, l, FQ, F2, P2, fcw, fcb, (float*)d_out);
}

// round 4
// speedup vs baseline: 1.0874x; 1.0874x over previous
#include <cuda_runtime.h>
#include <math.h>

#define NEG 0.01f
typedef unsigned long long ull;

// ---------------- packed f32x2 helpers ----------------
__device__ __forceinline__ ull pk2(float lo, float hi) {
    ull r; asm("mov.b64 %0,{%1,%2};" : "=l"(r) : "f"(lo), "f"(hi)); return r;
}
__device__ __forceinline__ void upk2(ull v, float& lo, float& hi) {
    asm("mov.b64 {%0,%1},%2;" : "=f"(lo), "=f"(hi) : "l"(v));
}
__device__ __forceinline__ ull ffma2(ull a, ull b, ull c) {
    ull d; asm("fma.rn.f32x2 %0,%1,%2,%3;" : "=l"(d) : "l"(a), "l"(b), "l"(c)); return d;
}

// ---------------- scratch (device globals; no runtime allocation) ----------------
__device__ float g_bufA[64L*256*2048];   // main activations
__device__ float g_bufB[64L*256*1024];   // conv1 output / flut-pvc conv scratch
__device__ float g_bufP[64L*256*1024];   // pooled identity input
__device__ float g_bufC[64L*256*1024];   // identity conv output
__device__ float g_qkv [64L*768*64];
__device__ float g_att [64L*256*64];
__device__ float g_hm  [64L*256*64];
__device__ float g_xmain[64*256];
__device__ float g_fvec[64*4096];
__device__ float g_pvec[64*2048];
__device__ float g_f2[64*64];
__device__ float g_p2[64*32];
__device__ float g_freq[64*32];
__device__ float2 g_tw[4096];
__device__ float g_bn[8192];
__device__ float g_wT[6535680];          // transposed weights

// g_wT offsets (floats)
#define O_CONV0   0L
#define O_RC1     46080L
#define O_RC2     2995200L
#define O_RID     5944320L
#define O_MHAIN   6272000L
#define O_MHAOUT  6468608L
#define O_FLUT    6534144L
#define O_PVC     6535104L

// ---------------- BN folding ----------------
__global__ void prep_kernel(const float* __restrict__ bn0,
                            const float* __restrict__ rbn1,
                            const float* __restrict__ rbn2,
                            const float* __restrict__ fbn, const float* __restrict__ fb,
                            const float* __restrict__ pbn, const float* __restrict__ pb)
{
    int c = threadIdx.x;
    if (c < 256) {
        {
            float g = bn0[c], b = bn0[256+c], m = bn0[512+c], v = bn0[768+c];
            float s = g * rsqrtf(v + 1e-5f);
            g_bn[c] = s; g_bn[256+c] = b - m*s;
        }
        for (int i = 0; i < 5; i++) {
            const float* p1 = rbn1 + i*1024;
            float g = p1[c], b = p1[256+c], m = p1[512+c], v = p1[768+c];
            float s = g * rsqrtf(v + 1e-5f);
            g_bn[512 + i*256 + c] = s; g_bn[1792 + i*256 + c] = b - m*s;
            const float* p2 = rbn2 + i*1024;
            g = p2[c]; b = p2[256+c]; m = p2[512+c]; v = p2[768+c];
            s = g * rsqrtf(v + 1e-5f);
            g_bn[3072 + i*256 + c] = s; g_bn[4352 + i*256 + c] = b - m*s;
        }
    }
    if (c < 64) {
        float g = fbn[c], b = fbn[64+c], m = fbn[128+c], v = fbn[192+c];
        float s = g * rsqrtf(v + 1e-5f);
        g_bn[5632+c] = s; g_bn[5696+c] = (fb[c] - m)*s + b;
        g = pbn[c]; b = pbn[64+c]; m = pbn[128+c]; v = pbn[192+c];
        s = g * rsqrtf(v + 1e-5f);
        g_bn[5760+c] = s; g_bn[5824+c] = (pb[c] - m)*s + b;
    }
}

// ---------------- weight transpose into SMEM-stage layout ----------------
__global__ void wtrans_kernel(const float* __restrict__ src, float* __restrict__ dst,
                              int CI, int KW, long total)
{
    long i = (long)blockIdx.x*256 + threadIdx.x;
    if (i >= total) return;
    int co64 = (int)(i & 63);
    long r = i >> 6;
    int k = (int)(r % KW); r /= KW;
    int ci = (int)(r % CI);
    long ct = r / CI;
    long co = ct*64 + co64;
    dst[i] = src[(co*CI + ci)*KW + k];
}

// ---------------- implicit-GEMM conv1d, f32x2 math, double-buffered staging ----------------
// 64co x 64t tile, 256 threads, 4co x 4t per thread.
template<int KW, int STRIDE, int CB>
__global__ void __launch_bounds__(256, 2) conv_gemm(
    const float* __restrict__ wT, const float* __restrict__ in,
    const float* __restrict__ scale, const float* __restrict__ bias,
    const float* __restrict__ addb, float* __restrict__ out, float* __restrict__ poolout,
    int CI, int CO, int Lin, int Lout, int pad, int dorelu, long inBS)
{
    constexpr int WIN  = 64*STRIDE + KW - 1;
    constexpr int WINP = (WIN + 11) & ~3;
    constexpr int RW   = 3*STRIDE + KW;
    constexpr int NV   = (RW + 3) / 4;
    __shared__ __align__(16) float sW[2][CB*KW*64];
    __shared__ __align__(16) float sIn[2][CB][WINP];

    const int tid = threadIdx.x;
    const int tx = tid & 15, ty = tid >> 4;
    const int t0 = blockIdx.x * 64, co0 = blockIdx.y * 64;
    const int b  = blockIdx.z;
    const float* inb = in + (long)b * inBS;
    const long wstride = (long)KW * 64;
    const float* wbase = wT + (long)blockIdx.y * CI * wstride;

    ull acc01[4], acc23[4];
    #pragma unroll
    for (int j = 0; j < 4; j++) { acc01[j] = 0ull; acc23[j] = 0ull; }

    const int nst = CI / CB;
    auto stage = [&](int buf, int cib) {
        const float4* ws = (const float4*)(wbase + (long)cib * wstride);
        float4* wd = (float4*)sW[buf];
        for (int idx = tid; idx < CB*KW*16; idx += 256) wd[idx] = ws[idx];
        for (int idx = tid; idx < CB*WIN; idx += 256) {
            int c = idx / WIN, w = idx - c*WIN;
            int g = t0*STRIDE - pad + w;
            sIn[buf][c][w] = (g >= 0 && g < Lin) ? __ldg(&inb[(long)(cib+c)*Lin + g]) : 0.f;
        }
    };

    stage(0, 0);
    __syncthreads();
    for (int s = 0; s < nst; s++) {
        int cur = s & 1;
        if (s + 1 < nst) stage(cur ^ 1, (s + 1) * CB);
        #pragma unroll
        for (int c = 0; c < CB; c++) {
            float4 wv4[NV];
            const float4* ip = (const float4*)&sIn[cur][c][tx*4*STRIDE];
            #pragma unroll
            for (int v = 0; v < NV; v++) wv4[v] = ip[v];
            const float* wf = (const float*)wv4;
            ull bc[RW];
            #pragma unroll
            for (int m = 0; m < RW; m++) bc[m] = pk2(wf[m], wf[m]);
            const float* wrow = sW[cur] + c*KW*64 + ty*4;   // 16B aligned
            #pragma unroll
            for (int k = 0; k < KW; k++) {
                ulonglong2 wv = *(const ulonglong2*)(wrow + k*64);
                #pragma unroll
                for (int j = 0; j < 4; j++) {
                    acc01[j] = ffma2(wv.x, bc[j*STRIDE + k], acc01[j]);
                    acc23[j] = ffma2(wv.y, bc[j*STRIDE + k], acc23[j]);
                }
            }
        }
        __syncthreads();
    }

    // epilogue
    float r[4][4];
    #pragma unroll
    for (int j = 0; j < 4; j++) { upk2(acc01[j], r[0][j], r[1][j]); upk2(acc23[j], r[2][j], r[3][j]); }
    #pragma unroll
    for (int i = 0; i < 4; i++) {
        int co = co0 + ty*4 + i;
        float sc = scale ? scale[co] : 1.f;
        float bb = bias  ? bias[co]  : 0.f;
        long obase = ((long)b*CO + co) * Lout + t0 + tx*4;
        float4 v;
        v.x = r[i][0]*sc + bb; v.y = r[i][1]*sc + bb;
        v.z = r[i][2]*sc + bb; v.w = r[i][3]*sc + bb;
        if (dorelu) {
            v.x = v.x >= 0.f ? v.x : NEG*v.x; v.y = v.y >= 0.f ? v.y : NEG*v.y;
            v.z = v.z >= 0.f ? v.z : NEG*v.z; v.w = v.w >= 0.f ? v.w : NEG*v.w;
        }
        if (addb) {
            float4 a = *(const float4*)&addb[obase];
            v.x += a.x; v.y += a.y; v.z += a.z; v.w += a.w;
        }
        *(float4*)&out[obase] = v;
        if (poolout) {
            long pbase = ((long)b*CO + co) * (Lout >> 1) + (t0 >> 1) + tx*2;
            *(float2*)&poolout[pbase] = make_float2(0.5f*(v.x + v.y), 0.5f*(v.z + v.w));
        }
    }
}

// ---------------- attention per (batch, head): S=64, d=32 ----------------
__global__ void __launch_bounds__(128) attn_kernel(const float* __restrict__ qkv,
                                                   float* __restrict__ out)
{
    __shared__ float q[32][64], kk[32][64], vv[32][64];
    __shared__ float att[64][65];
    int bh = blockIdx.x; int b = bh >> 3, h = bh & 7;
    const float* base = qkv + (long)b*768*64 + (long)h*32*64;
    int tid = threadIdx.x;
    for (int idx = tid; idx < 2048; idx += 128) {
        int d = idx >> 6, s = idx & 63;
        q [d][s] = base[d*64 + s];
        kk[d][s] = base[256*64 + d*64 + s];
        vv[d][s] = base[512*64 + d*64 + s];
    }
    __syncthreads();
    for (int e = tid; e < 4096; e += 128) {
        int qs = e >> 6, ks = e & 63;
        float s = 0.f;
        #pragma unroll
        for (int d = 0; d < 32; d++) s = fmaf(q[d][qs], kk[d][ks], s);
        att[qs][ks] = s * 0.17677669529663687f;
    }
    __syncthreads();
    if (tid < 64) {
        float m = -1e30f;
        for (int ks = 0; ks < 64; ks++) m = fmaxf(m, att[tid][ks]);
        float sum = 0.f;
        for (int ks = 0; ks < 64; ks++) { float e = expf(att[tid][ks] - m); att[tid][ks] = e; sum += e; }
        float inv = 1.f / sum;
        for (int ks = 0; ks < 64; ks++) att[tid][ks] *= inv;
    }
    __syncthreads();
    float* ob = out + (long)b*256*64 + (long)h*32*64;
    for (int e = tid; e < 2048; e += 128) {
        int d = e >> 6, qs = e & 63;
        float s = 0.f;
        #pragma unroll
        for (int ks = 0; ks < 64; ks++) s = fmaf(att[qs][ks], vv[d][ks], s);
        ob[d*64 + qs] = s;
    }
}

// ---------------- max over t (T=64) ----------------
__global__ void max_t_kernel(const float* __restrict__ in, float* __restrict__ out)
{
    int b = blockIdx.x, c = threadIdx.x;
    const float* r = in + ((long)b*256 + c) * 64;
    float m = r[0];
    #pragma unroll
    for (int t = 1; t < 64; t++) m = fmaxf(m, r[t]);
    out[b*256 + c] = m;
}

// ---------------- grouped max along L ----------------
__global__ void group_max_kernel(const float* __restrict__ in, float* __restrict__ out, int GS)
{
    int row = blockIdx.x; int g = threadIdx.x; int G = blockDim.x;
    const float* r = in + (long)row*G*GS + (long)g*GS;
    float m = r[0];
    for (int j = 1; j < GS; j++) m = fmaxf(m, r[j]);
    out[(long)row*G + g] = m;
}

// ---------------- small dense (per-batch) ----------------
__global__ void dense_kernel(const float* __restrict__ in, const float* __restrict__ w,
                             const float* __restrict__ bias, float* __restrict__ out,
                             int IN, int OUT, int dorelu)
{
    int b = blockIdx.x, o = threadIdx.x;
    if (o >= OUT) return;
    const float* iv = in + (long)b*IN;
    const float* wr = w + (long)o*IN;
    float s = bias ? bias[o] : 0.f;
    for (int i = 0; i < IN; i++) s = fmaf(iv[i], wr[i], s);
    if (dorelu) s = (s >= 0.f) ? s : NEG*s;
    out[b*OUT + o] = s;
}

// ---------------- twiddle table ----------------
__global__ void twiddle_kernel()
{
    int i = blockIdx.x*256 + threadIdx.x;
    if (i < 4096) {
        double a = -2.0 * 3.14159265358979323846 * (double)i / 4096.0;
        g_tw[i] = make_float2((float)cos(a), (float)sin(a));
    }
}

// ---------------- DFT bins 50..305 + normalize + freq dense ----------------
__global__ void __launch_bounds__(256) fft_freq_kernel(const float* __restrict__ x,
                                                       const float* __restrict__ fw,
                                                       const float* __restrict__ fb,
                                                       float* __restrict__ out)
{
    __shared__ float2 stw[4096];
    __shared__ float smag[256];
    __shared__ float sred[256];
    int b = blockIdx.x, tid = threadIdx.x;
    for (int i = tid; i < 4096; i += 256) stw[i] = g_tw[i];
    const float* xr = x + ((long)b*12 + 1) * 4096;
    __syncthreads();
    int k = 50 + tid;
    float re = 0.f, im = 0.f;
    for (int n = 0; n < 4096; n++) {
        float xv = __ldg(&xr[n]);
        float2 c = stw[(k*n) & 4095];
        re = fmaf(xv, c.x, re);
        im = fmaf(xv, c.y, im);
    }
    float mag = sqrtf(re*re + im*im);
    smag[tid] = mag; sred[tid] = mag;
    __syncthreads();
    for (int s = 128; s > 0; s >>= 1) {
        if (tid < s) sred[tid] = fmaxf(sred[tid], sred[tid+s]);
        __syncthreads();
    }
    float mx = sred[0];
    smag[tid] = (mx > 0.f) ? mag/mx : mag;
    __syncthreads();
    if (tid < 32) {
        float s = fb[tid];
        const float* wr = fw + tid*256;
        for (int j = 0; j < 256; j++) s = fmaf(smag[j], wr[j], s);
        out[b*32 + tid] = (s >= 0.f) ? s : NEG*s;
    }
}

// ---------------- concat + FC + sigmoid ----------------
__global__ void final_kernel(const float* __restrict__ xm, const float* __restrict__ l,
                             const float* __restrict__ fq, const float* __restrict__ f2,
                             const float* __restrict__ p2, const float* __restrict__ fcw,
                             const float* __restrict__ fcb, float* __restrict__ out)
{
    __shared__ float comb[396];
    int b = blockIdx.x, tid = threadIdx.x;
    for (int i = tid; i < 256; i += 128) comb[i] = xm[b*256 + i];
    if (tid < 12) comb[256 + tid] = l[b*12 + tid];
    if (tid < 32) comb[268 + tid] = fq[b*32 + tid];
    if (tid < 64) comb[300 + tid] = f2[b*64 + tid];
    if (tid < 32) comb[364 + tid] = p2[b*32 + tid];
    __syncthreads();
    if (tid < 27) {
        float s = fcb[tid];
        const float* wr = fcw + tid*396;
        for (int j = 0; j < 396; j++) s = fmaf(comb[j], wr[j], s);
        out[b*27 + tid] = s;
        out[64*27 + b*27 + tid] = 1.f / (1.f + expf(-s));
    }
}

// ---------------- host launch ----------------
extern "C" void kernel_launch(void* const* d_in, const int* in_sizes, int n_in,
                              void* d_out, int out_size)
{
    (void)in_sizes; (void)n_in; (void)out_size;
    const float* x      = (const float*)d_in[0];
    const float* l      = (const float*)d_in[1];
    const float* conv_w = (const float*)d_in[2];
    const float* bn0    = (const float*)d_in[3];
    const float* rc1    = (const float*)d_in[4];
    const float* rbn1   = (const float*)d_in[5];
    const float* rc2    = (const float*)d_in[6];
    const float* rbn2   = (const float*)d_in[7];
    const float* rid    = (const float*)d_in[8];
    const float* miw    = (const float*)d_in[9];
    const float* mib    = (const float*)d_in[10];
    const float* mow    = (const float*)d_in[11];
    const float* mob    = (const float*)d_in[12];
    const float* fw     = (const float*)d_in[13];
    const float* fbv    = (const float*)d_in[14];
    const float* fbn    = (const float*)d_in[15];
    const float* pw     = (const float*)d_in[16];
    const float* pbv    = (const float*)d_in[17];
    const float* pbn    = (const float*)d_in[18];
    const float* wflut2 = (const float*)d_in[19];
    const float* wpvc2  = (const float*)d_in[20];
    const float* freqw  = (const float*)d_in[21];
    const float* freqb  = (const float*)d_in[22];
    const float* fcw    = (const float*)d_in[23];
    const float* fcb    = (const float*)d_in[24];

    float *A, *Bf, *P, *C, *QKV, *ATT, *HM, *XM, *FV, *PV, *F2, *P2, *FQ, *BN, *WT;
    cudaGetSymbolAddress((void**)&A,   g_bufA);
    cudaGetSymbolAddress((void**)&Bf,  g_bufB);
    cudaGetSymbolAddress((void**)&P,   g_bufP);
    cudaGetSymbolAddress((void**)&C,   g_bufC);
    cudaGetSymbolAddress((void**)&QKV, g_qkv);
    cudaGetSymbolAddress((void**)&ATT, g_att);
    cudaGetSymbolAddress((void**)&HM,  g_hm);
    cudaGetSymbolAddress((void**)&XM,  g_xmain);
    cudaGetSymbolAddress((void**)&FV,  g_fvec);
    cudaGetSymbolAddress((void**)&PV,  g_pvec);
    cudaGetSymbolAddress((void**)&F2,  g_f2);
    cudaGetSymbolAddress((void**)&P2,  g_p2);
    cudaGetSymbolAddress((void**)&FQ,  g_freq);
    cudaGetSymbolAddress((void**)&BN,  g_bn);
    cudaGetSymbolAddress((void**)&WT,  g_wT);

    prep_kernel<<<1, 256>>>(bn0, rbn1, rbn2, fbn, fbv, pbn, pbv);
    twiddle_kernel<<<16, 256>>>();

    auto wt = [&](const float* src, long off, int CO, int CI, int KW) {
        long tot = (long)CO*CI*KW;
        wtrans_kernel<<<(unsigned)((tot + 255)/256), 256>>>(src, WT + off, CI, KW, tot);
    };
    wt(conv_w, O_CONV0, 256, 12, 15);
    wt(rc1,    O_RC1,   1280, 256, 9);
    wt(rc2,    O_RC2,   1280, 256, 9);
    wt(rid,    O_RID,   1280, 256, 1);
    wt(miw,    O_MHAIN,  768, 256, 1);
    wt(mow,    O_MHAOUT, 256, 256, 1);
    wt(fw,     O_FLUT,    64,   1, 15);
    wt(pw,     O_PVC,     64,   1, 9);

    // conv0: (B,12,4096) -> (B,256,2048), fused avgpool2 -> P
    conv_gemm<15,2,4><<<dim3(32,4,64), 256>>>(WT+O_CONV0, x, BN+0, BN+256, nullptr, A, P,
                                              12, 256, 4096, 2048, 7, 1, 12L*4096);

    int L = 2048;
    for (int i = 0; i < 5; i++) {
        int Lh = L/2;
        conv_gemm<9,2,8><<<dim3(Lh/64,4,64), 256>>>(WT+O_RC1 + (long)i*589824, A,
                                                    BN+512+i*256, BN+1792+i*256, nullptr, Bf, nullptr,
                                                    256, 256, L, Lh, 4, 1, 256L*L);
        conv_gemm<1,1,16><<<dim3(Lh/64,4,64), 256>>>(WT+O_RID + (long)i*65536, P,
                                                     nullptr, nullptr, nullptr, C, nullptr,
                                                     256, 256, Lh, Lh, 0, 0, 256L*Lh);
        conv_gemm<9,1,8><<<dim3(Lh/64,4,64), 256>>>(WT+O_RC2 + (long)i*589824, Bf,
                                                    BN+3072+i*256, BN+4352+i*256, C, A, P,
                                                    256, 256, Lh, Lh, 4, 1, 256L*Lh);
        L = Lh;
    }

    // MHA
    conv_gemm<1,1,16><<<dim3(1,12,64), 256>>>(WT+O_MHAIN, A, nullptr, mib, nullptr, QKV, nullptr,
                                              256, 768, 64, 64, 0, 0, 256L*64);
    attn_kernel<<<512, 128>>>(QKV, ATT);
    conv_gemm<1,1,16><<<dim3(1,4,64), 256>>>(WT+O_MHAOUT, ATT, nullptr, mob, nullptr, HM, nullptr,
                                             256, 256, 64, 64, 0, 0, 256L*64);
    max_t_kernel<<<64, 256>>>(HM, XM);

    // FLUT path (lead II)
    conv_gemm<15,2,1><<<dim3(32,1,64), 256>>>(WT+O_FLUT, x + 4096, BN+5632, BN+5696, nullptr, Bf, nullptr,
                                              1, 64, 4096, 2048, 7, 1, 12L*4096);
    group_max_kernel<<<64*64, 64>>>(Bf, FV, 32);
    dense_kernel<<<64, 64>>>(FV, wflut2, nullptr, F2, 4096, 64, 1);

    // PVC path
    conv_gemm<9,2,1><<<dim3(32,1,64), 256>>>(WT+O_PVC, x + 4096, BN+5760, BN+5824, nullptr, Bf, nullptr,
                                             1, 64, 4096, 2048, 4, 1, 12L*4096);
    group_max_kernel<<<64*64, 32>>>(Bf, PV, 64);
    dense_kernel<<<64, 64>>>(PV, wpvc2, nullptr, P2, 2048, 32, 1);

    // FFT + freq dense
    fft_freq_kernel<<<64, 256>>>(x, freqw, freqb, FQ);

    // concat + FC + sigmoid
    final_kernel<<<64, 128>>>(XM, l, FQ, F2, P2, fcw, fcb, (float*)d_out);
}